// round 1
// baseline (speedup 1.0000x reference)
#include <cuda_runtime.h>

// ---------------------------------------------------------------------------
// PyG HypergraphConv (use_attention=False, heads=1):
//   out = (Dinv ⊙ H · Binv · Hᵀ · x) @ W + b        (W commutes to the end)
// N = E = 50000, NNZ = 500000, F = 256 (capacities fixed below)
// ---------------------------------------------------------------------------

#define MAXN   50000
#define MAXNNZ 500000
#define DF     256

__device__ float g_esum[MAXN * DF];   // per-edge feature sums  (51.2 MB)
__device__ float g_agg [MAXN * DF];   // per-node aggregate     (51.2 MB)
__device__ float g_Dinv[MAXN];
__device__ float g_Binv[MAXN];
__device__ int   g_node[MAXNNZ];
__device__ int   g_edge[MAXNNZ];
__device__ int   g_is64;

// --- detect whether hyperedge_index is int64 or int32 ----------------------
// int64 values < 50000 => every odd 32-bit word of the first entries is 0.
// For int32 data those words are random node ids; P(all zero) ~ (1/50000)^128.
__global__ void k_detect(const unsigned int* __restrict__ raw) {
    if (threadIdx.x == 0 && blockIdx.x == 0) {
        int is64 = 1;
        #pragma unroll 1
        for (int k = 1; k < 256; k += 2)
            if (raw[k] != 0u) { is64 = 0; break; }
        g_is64 = is64;
    }
}

__global__ void k_convert(const void* __restrict__ raw, int nnz) {
    int i = blockIdx.x * blockDim.x + threadIdx.x;
    if (i >= nnz) return;
    if (g_is64) {
        const long long* p = (const long long*)raw;
        g_node[i] = (int)p[i];
        g_edge[i] = (int)p[nnz + i];
    } else {
        const int* p = (const int*)raw;
        g_node[i] = p[i];
        g_edge[i] = p[nnz + i];
    }
}

// --- zeroing ----------------------------------------------------------------
__global__ void k_zero_small(int n) {
    int i = blockIdx.x * blockDim.x + threadIdx.x;
    if (i < n) { g_Dinv[i] = 0.f; g_Binv[i] = 0.f; }
}

__global__ void k_zero_feat(int n4) {  // n4 = rows*256/4
    int i = blockIdx.x * blockDim.x + threadIdx.x;
    if (i < n4) {
        float4 z = make_float4(0.f, 0.f, 0.f, 0.f);
        ((float4*)g_esum)[i] = z;
        ((float4*)g_agg )[i] = z;
    }
}

// --- degrees ------------------------------------------------------------------
__global__ void k_deg(const float* __restrict__ w, int nnz) {
    int i = blockIdx.x * blockDim.x + threadIdx.x;
    if (i >= nnz) return;
    int node = g_node[i];
    int edge = g_edge[i];
    atomicAdd(&g_Dinv[node], __ldg(&w[edge]));   // D[i]  = sum of incident edge weights
    atomicAdd(&g_Binv[edge], 1.0f);              // B[e]  = cardinality
}

__global__ void k_recip(int N, int E) {
    int i = blockIdx.x * blockDim.x + threadIdx.x;
    if (i < N) { float d = g_Dinv[i]; g_Dinv[i] = (d > 0.f) ? 1.0f / d : 0.f; }
    if (i < E) { float c = g_Binv[i]; g_Binv[i] = (c > 0.f) ? 1.0f / c : 0.f; }
}

// --- vector reduction (no-return atomic add, 16B) ----------------------------
__device__ __forceinline__ void red_add_v4(float* p, float4 v) {
    asm volatile("red.global.add.v4.f32 [%0], {%1,%2,%3,%4};"
                 :: "l"(p), "f"(v.x), "f"(v.y), "f"(v.z), "f"(v.w)
                 : "memory");
}

// --- phase 1: e_sum[e] += x[i]  (64 threads per incidence entry) --------------
__global__ void k_scatter1(const float* __restrict__ x, int nnz) {
    int t    = blockIdx.x * blockDim.x + threadIdx.x;
    int item = t >> 6;
    int lane = t & 63;
    if (item >= nnz) return;
    int node = g_node[item];
    int edge = g_edge[item];
    float4 v = __ldg((const float4*)x + (size_t)node * 64 + lane);
    red_add_v4(&g_esum[(size_t)edge * 256 + lane * 4], v);
}

// --- phase 2: agg[i] += Dinv[i]*Binv[e]*e_sum[e] ------------------------------
__global__ void k_scatter2(int nnz) {
    int t    = blockIdx.x * blockDim.x + threadIdx.x;
    int item = t >> 6;
    int lane = t & 63;
    if (item >= nnz) return;
    int node = g_node[item];
    int edge = g_edge[item];
    float s  = g_Dinv[node] * g_Binv[edge];
    float4 v = ((const float4*)g_esum)[(size_t)edge * 64 + lane];
    v.x *= s; v.y *= s; v.z *= s; v.w *= s;
    red_add_v4(&g_agg[(size_t)node * 256 + lane * 4], v);
}

// --- final GEMM: out = agg @ W + b  (M x 256 x 256, fp32 SIMT) -----------------
// 128x128 block tile, BK=8, 256 threads, 8x8 per thread (4+4 split layout).
__global__ void __launch_bounds__(256, 2) k_gemm_bias(
    const float* __restrict__ B,     // W [256,256] row-major
    const float* __restrict__ bias,  // [256]
    float* __restrict__ C,           // out [M,256]
    int M)
{
    const int K = 256, N = 256;
    __shared__ float As[8][128];
    __shared__ float Bs[8][128];

    int tid = threadIdx.x;
    int bm  = blockIdx.y * 128;
    int bn  = blockIdx.x * 128;
    int tx  = tid & 15;
    int ty  = tid >> 4;

    const float* A = g_agg;

    float acc[8][8];
    #pragma unroll
    for (int i = 0; i < 8; i++)
        #pragma unroll
        for (int j = 0; j < 8; j++) acc[i][j] = 0.f;

    int arow = tid >> 1;          // 0..127
    int acol = (tid & 1) * 4;     // 0 or 4
    int brow = tid >> 5;          // 0..7
    int bcol = (tid & 31) * 4;    // 0..124

    for (int k0 = 0; k0 < K; k0 += 8) {
        float4 a4 = make_float4(0.f, 0.f, 0.f, 0.f);
        int gr = bm + arow;
        if (gr < M) a4 = *(const float4*)(A + (size_t)gr * K + k0 + acol);
        As[acol + 0][arow] = a4.x;
        As[acol + 1][arow] = a4.y;
        As[acol + 2][arow] = a4.z;
        As[acol + 3][arow] = a4.w;
        *(float4*)&Bs[brow][bcol] =
            *(const float4*)(B + (size_t)(k0 + brow) * N + bn + bcol);
        __syncthreads();

        #pragma unroll
        for (int kk = 0; kk < 8; kk++) {
            float a[8], b[8];
            *(float4*)&a[0] = *(const float4*)&As[kk][ty * 4];
            *(float4*)&a[4] = *(const float4*)&As[kk][ty * 4 + 64];
            *(float4*)&b[0] = *(const float4*)&Bs[kk][tx * 4];
            *(float4*)&b[4] = *(const float4*)&Bs[kk][tx * 4 + 64];
            #pragma unroll
            for (int i = 0; i < 8; i++)
                #pragma unroll
                for (int j = 0; j < 8; j++)
                    acc[i][j] += a[i] * b[j];
        }
        __syncthreads();
    }

    #pragma unroll
    for (int ih = 0; ih < 2; ih++) {
        #pragma unroll
        for (int i = 0; i < 4; i++) {
            int gr = bm + ih * 64 + ty * 4 + i;
            if (gr >= M) continue;
            #pragma unroll
            for (int jh = 0; jh < 2; jh++) {
                int gc = bn + jh * 64 + tx * 4;
                float4 o;
                o.x = acc[ih * 4 + i][jh * 4 + 0] + __ldg(&bias[gc + 0]);
                o.y = acc[ih * 4 + i][jh * 4 + 1] + __ldg(&bias[gc + 1]);
                o.z = acc[ih * 4 + i][jh * 4 + 2] + __ldg(&bias[gc + 2]);
                o.w = acc[ih * 4 + i][jh * 4 + 3] + __ldg(&bias[gc + 3]);
                *(float4*)(C + (size_t)gr * N + gc) = o;
            }
        }
    }
}

// ---------------------------------------------------------------------------
extern "C" void kernel_launch(void* const* d_in, const int* in_sizes, int n_in,
                              void* d_out, int out_size) {
    const float* x    = (const float*)d_in[0];   // [N,256]
    const void*  hidx = d_in[1];                 // [2,NNZ] int32 or int64
    const float* hw   = (const float*)d_in[2];   // [E]
    const float* W    = (const float*)d_in[3];   // [256,256]
    const float* bias = (const float*)d_in[4];   // [256]
    float*       out  = (float*)d_out;           // [N,256]

    int N   = in_sizes[0] / 256;
    int NNZ = in_sizes[1] / 2;
    int E   = in_sizes[2];
    int NE  = (N > E) ? N : E;

    k_detect<<<1, 32>>>((const unsigned int*)hidx);
    k_convert<<<(NNZ + 255) / 256, 256>>>(hidx, NNZ);

    k_zero_small<<<(NE + 255) / 256, 256>>>(NE);
    int n4 = NE * 64;  // NE*256/4 float4s
    k_zero_feat<<<(n4 + 255) / 256, 256>>>(n4);

    k_deg<<<(NNZ + 255) / 256, 256>>>(hw, NNZ);
    k_recip<<<(NE + 255) / 256, 256>>>(N, E);

    long long th = (long long)NNZ * 64;
    int sblocks  = (int)((th + 255) / 256);
    k_scatter1<<<sblocks, 256>>>(x, NNZ);
    k_scatter2<<<sblocks, 256>>>(NNZ);

    dim3 g(2, (N + 127) / 128);
    k_gemm_bias<<<g, 256>>>(W, bias, out, N);
}

// round 2
// speedup vs baseline: 1.5410x; 1.5410x over previous
#include <cuda_runtime.h>

// ---------------------------------------------------------------------------
// PyG HypergraphConv (use_attention=False, heads=1):
//   out = (Dinv ⊙ H · Binv · Hᵀ · x) @ W + b        (W commutes to the end)
// CSR-based two-phase aggregation: no feature atomics, no feature zeroing.
// ---------------------------------------------------------------------------

#define MAXN   50000
#define MAXNNZ 500000

__device__ float g_esum[MAXN * 256];
__device__ float g_agg [MAXN * 256];
__device__ float g_Dinv[MAXN];
__device__ int   g_node[MAXNNZ];
__device__ int   g_edge[MAXNNZ];
__device__ int   g_adj_e[MAXNNZ];
__device__ int   g_adj_n[MAXNNZ];
__device__ int   g_off_e[MAXN + 1];
__device__ int   g_off_n[MAXN + 1];
__device__ int   g_cur_e[MAXN];
__device__ int   g_cur_n[MAXN];
__device__ int   g_bsum[256];
__device__ int   g_is64;

// --- dtype detection: int64 values < 2^31 have zero odd 32-bit words ---------
__global__ void k_detect(const unsigned int* __restrict__ raw) {
    if (threadIdx.x == 0 && blockIdx.x == 0) {
        int is64 = 1;
        #pragma unroll 1
        for (int k = 1; k < 256; k += 2)
            if (raw[k] != 0u) { is64 = 0; break; }
        g_is64 = is64;
    }
}

__global__ void k_convert(const void* __restrict__ raw, int nnz) {
    int i = blockIdx.x * blockDim.x + threadIdx.x;
    if (i >= nnz) return;
    if (g_is64) {
        const long long* p = (const long long*)raw;
        g_node[i] = (int)p[i];
        g_edge[i] = (int)p[nnz + i];
    } else {
        const int* p = (const int*)raw;
        g_node[i] = p[i];
        g_edge[i] = p[nnz + i];
    }
}

// --- CSR build ----------------------------------------------------------------
__global__ void k_zero_off(int n) {
    int i = blockIdx.x * blockDim.x + threadIdx.x;
    if (i <= n) { g_off_e[i] = 0; g_off_n[i] = 0; }
}

__global__ void k_hist(int nnz) {
    int i = blockIdx.x * blockDim.x + threadIdx.x;
    if (i >= nnz) return;
    atomicAdd(&g_off_e[g_edge[i]], 1);
    atomicAdd(&g_off_n[g_node[i]], 1);
}

#define SCAN_B 1024
__global__ void k_scan_blk(int* __restrict__ a, int n) {
    __shared__ int sh[SCAN_B];
    int i = blockIdx.x * SCAN_B + threadIdx.x;
    int v = (i < n) ? a[i] : 0;
    sh[threadIdx.x] = v;
    __syncthreads();
    #pragma unroll 1
    for (int d = 1; d < SCAN_B; d <<= 1) {
        int t = (threadIdx.x >= d) ? sh[threadIdx.x - d] : 0;
        __syncthreads();
        sh[threadIdx.x] += t;
        __syncthreads();
    }
    if (i < n) a[i] = sh[threadIdx.x] - v;   // exclusive
    if (threadIdx.x == SCAN_B - 1) g_bsum[blockIdx.x] = sh[SCAN_B - 1];
}

__global__ void k_scan_top(int nb) {
    __shared__ int sh[256];
    int v = (threadIdx.x < nb) ? g_bsum[threadIdx.x] : 0;
    sh[threadIdx.x] = v;
    __syncthreads();
    #pragma unroll 1
    for (int d = 1; d < 256; d <<= 1) {
        int t = (threadIdx.x >= d) ? sh[threadIdx.x - d] : 0;
        __syncthreads();
        sh[threadIdx.x] += t;
        __syncthreads();
    }
    if (threadIdx.x < nb) g_bsum[threadIdx.x] = sh[threadIdx.x] - v;
}

__global__ void k_scan_add(int* __restrict__ a, int* __restrict__ cur,
                           int n, int nnz) {
    int i = blockIdx.x * blockDim.x + threadIdx.x;
    if (i < n) {
        int o = a[i] + g_bsum[i >> 10];
        a[i] = o;
        cur[i] = o;
    }
    if (i == 0) a[n] = nnz;
}

__global__ void k_fill(int nnz) {
    int i = blockIdx.x * blockDim.x + threadIdx.x;
    if (i >= nnz) return;
    int node = g_node[i];
    int edge = g_edge[i];
    int p = atomicAdd(&g_cur_e[edge], 1);
    g_adj_e[p] = node;
    int q = atomicAdd(&g_cur_n[node], 1);
    g_adj_n[q] = edge;
}

// --- Dinv ----------------------------------------------------------------------
__global__ void k_dinv(const float* __restrict__ w, int N) {
    int i = blockIdx.x * blockDim.x + threadIdx.x;
    if (i >= N) return;
    int s = g_off_n[i], t = g_off_n[i + 1];
    float d = 0.f;
    for (int j = s; j < t; j++) d += __ldg(&w[g_adj_n[j]]);
    g_Dinv[i] = (d > 0.f) ? 1.0f / d : 0.f;
}

// --- phase 1: esum[e] = Binv[e] * sum_{i in e} x[i] ----------------------------
__global__ void __launch_bounds__(256) k_phase1(const float4* __restrict__ x4, int E) {
    int g    = (blockIdx.x * blockDim.x + threadIdx.x) >> 5;
    int lane = threadIdx.x & 31;
    if (g >= E) return;
    int s = g_off_e[g], t = g_off_e[g + 1];
    float4 a0 = make_float4(0.f, 0.f, 0.f, 0.f);
    float4 a1 = make_float4(0.f, 0.f, 0.f, 0.f);
    #pragma unroll 2
    for (int j = s; j < t; j++) {
        const float4* r = x4 + (size_t)g_adj_e[j] * 64;
        float4 v0 = __ldg(r + lane);
        float4 v1 = __ldg(r + lane + 32);
        a0.x += v0.x; a0.y += v0.y; a0.z += v0.z; a0.w += v0.w;
        a1.x += v1.x; a1.y += v1.y; a1.z += v1.z; a1.w += v1.w;
    }
    float binv = (t > s) ? 1.0f / (float)(t - s) : 0.f;
    a0.x *= binv; a0.y *= binv; a0.z *= binv; a0.w *= binv;
    a1.x *= binv; a1.y *= binv; a1.z *= binv; a1.w *= binv;
    float4* o = (float4*)g_esum + (size_t)g * 64;
    o[lane]      = a0;
    o[lane + 32] = a1;
}

// --- phase 2: agg[i] = Dinv[i] * sum_{e ∋ i} esum[e] ---------------------------
__global__ void __launch_bounds__(256) k_phase2(int N) {
    int g    = (blockIdx.x * blockDim.x + threadIdx.x) >> 5;
    int lane = threadIdx.x & 31;
    if (g >= N) return;
    int s = g_off_n[g], t = g_off_n[g + 1];
    float4 a0 = make_float4(0.f, 0.f, 0.f, 0.f);
    float4 a1 = make_float4(0.f, 0.f, 0.f, 0.f);
    #pragma unroll 2
    for (int j = s; j < t; j++) {
        const float4* r = (const float4*)g_esum + (size_t)g_adj_n[j] * 64;
        float4 v0 = __ldg(r + lane);
        float4 v1 = __ldg(r + lane + 32);
        a0.x += v0.x; a0.y += v0.y; a0.z += v0.z; a0.w += v0.w;
        a1.x += v1.x; a1.y += v1.y; a1.z += v1.z; a1.w += v1.w;
    }
    float dinv = g_Dinv[g];
    a0.x *= dinv; a0.y *= dinv; a0.z *= dinv; a0.w *= dinv;
    a1.x *= dinv; a1.y *= dinv; a1.z *= dinv; a1.w *= dinv;
    float4* o = (float4*)g_agg + (size_t)g * 64;
    o[lane]      = a0;
    o[lane + 32] = a1;
}

// --- final GEMM: out = agg @ W + b  (M x 256 x 256, fp32 SIMT) -----------------
__global__ void __launch_bounds__(256, 2) k_gemm_bias(
    const float* __restrict__ B, const float* __restrict__ bias,
    float* __restrict__ C, int M)
{
    const int K = 256, N = 256;
    __shared__ float As[8][128];
    __shared__ float Bs[8][128];

    int tid = threadIdx.x;
    int bm  = blockIdx.y * 128;
    int bn  = blockIdx.x * 128;
    int tx  = tid & 15;
    int ty  = tid >> 4;

    const float* A = g_agg;

    float acc[8][8];
    #pragma unroll
    for (int i = 0; i < 8; i++)
        #pragma unroll
        for (int j = 0; j < 8; j++) acc[i][j] = 0.f;

    int arow = tid >> 1;
    int acol = (tid & 1) * 4;
    int brow = tid >> 5;
    int bcol = (tid & 31) * 4;

    for (int k0 = 0; k0 < K; k0 += 8) {
        float4 a4 = make_float4(0.f, 0.f, 0.f, 0.f);
        int gr = bm + arow;
        if (gr < M) a4 = *(const float4*)(A + (size_t)gr * K + k0 + acol);
        As[acol + 0][arow] = a4.x;
        As[acol + 1][arow] = a4.y;
        As[acol + 2][arow] = a4.z;
        As[acol + 3][arow] = a4.w;
        *(float4*)&Bs[brow][bcol] =
            *(const float4*)(B + (size_t)(k0 + brow) * N + bn + bcol);
        __syncthreads();

        #pragma unroll
        for (int kk = 0; kk < 8; kk++) {
            float a[8], b[8];
            *(float4*)&a[0] = *(const float4*)&As[kk][ty * 4];
            *(float4*)&a[4] = *(const float4*)&As[kk][ty * 4 + 64];
            *(float4*)&b[0] = *(const float4*)&Bs[kk][tx * 4];
            *(float4*)&b[4] = *(const float4*)&Bs[kk][tx * 4 + 64];
            #pragma unroll
            for (int i = 0; i < 8; i++)
                #pragma unroll
                for (int j = 0; j < 8; j++)
                    acc[i][j] += a[i] * b[j];
        }
        __syncthreads();
    }

    #pragma unroll
    for (int ih = 0; ih < 2; ih++) {
        #pragma unroll
        for (int i = 0; i < 4; i++) {
            int gr = bm + ih * 64 + ty * 4 + i;
            if (gr >= M) continue;
            #pragma unroll
            for (int jh = 0; jh < 2; jh++) {
                int gc = bn + jh * 64 + tx * 4;
                float4 o;
                o.x = acc[ih * 4 + i][jh * 4 + 0] + __ldg(&bias[gc + 0]);
                o.y = acc[ih * 4 + i][jh * 4 + 1] + __ldg(&bias[gc + 1]);
                o.z = acc[ih * 4 + i][jh * 4 + 2] + __ldg(&bias[gc + 2]);
                o.w = acc[ih * 4 + i][jh * 4 + 3] + __ldg(&bias[gc + 3]);
                *(float4*)(C + (size_t)gr * N + gc) = o;
            }
        }
    }
}

// ---------------------------------------------------------------------------
static int* sym_ptr(const void* sym) {
    void* p = nullptr;
    cudaGetSymbolAddress(&p, sym);
    return (int*)p;
}

extern "C" void kernel_launch(void* const* d_in, const int* in_sizes, int n_in,
                              void* d_out, int out_size) {
    const float* x    = (const float*)d_in[0];
    const void*  hidx = d_in[1];
    const float* hw   = (const float*)d_in[2];
    const float* W    = (const float*)d_in[3];
    const float* bias = (const float*)d_in[4];
    float*       out  = (float*)d_out;

    int N   = in_sizes[0] / 256;
    int NNZ = in_sizes[1] / 2;
    int E   = in_sizes[2];
    int NE  = (N > E) ? N : E;

    int* p_off_e = sym_ptr(g_off_e);
    int* p_off_n = sym_ptr(g_off_n);
    int* p_cur_e = sym_ptr(g_cur_e);
    int* p_cur_n = sym_ptr(g_cur_n);

    k_detect<<<1, 32>>>((const unsigned int*)hidx);
    k_convert<<<(NNZ + 255) / 256, 256>>>(hidx, NNZ);

    k_zero_off<<<(NE + 256) / 256, 256>>>(NE);
    k_hist<<<(NNZ + 255) / 256, 256>>>(NNZ);

    int nbE = (E + SCAN_B - 1) / SCAN_B;
    k_scan_blk<<<nbE, SCAN_B>>>(p_off_e, E);
    k_scan_top<<<1, 256>>>(nbE);
    k_scan_add<<<(E + 255) / 256, 256>>>(p_off_e, p_cur_e, E, NNZ);

    int nbN = (N + SCAN_B - 1) / SCAN_B;
    k_scan_blk<<<nbN, SCAN_B>>>(p_off_n, N);
    k_scan_top<<<1, 256>>>(nbN);
    k_scan_add<<<(N + 255) / 256, 256>>>(p_off_n, p_cur_n, N, NNZ);

    k_fill<<<(NNZ + 255) / 256, 256>>>(NNZ);
    k_dinv<<<(N + 255) / 256, 256>>>(hw, N);

    k_phase1<<<(E * 32 + 255) / 256, 256>>>((const float4*)x, E);
    k_phase2<<<(N * 32 + 255) / 256, 256>>>(N);

    dim3 g(2, (N + 127) / 128);
    k_gemm_bias<<<g, 256>>>(W, bias, out, N);
}

// round 4
// speedup vs baseline: 2.0348x; 1.3204x over previous
#include <cuda_runtime.h>
#include <cuda_fp16.h>
#include <cstdint>

// ---------------------------------------------------------------------------
// PyG HypergraphConv:  out = (Dinv ⊙ H · Binv · Hᵀ · x) @ W + b
// CSR two-phase aggregation + mma.sync fp16 hi/lo split GEMM (baseline PTX —
// tcgen05 is unavailable: harness compiles to compute_103, no 'a' features).
// ---------------------------------------------------------------------------

#define MAXN   50000
#define MAXNNZ 500000

__device__ float  g_esum[MAXN * 256];
__device__ __half g_Ah[MAXN * 512];   // [M][512] = [hi(256) | lo(256)]
__device__ __half g_Bh[256 * 512];    // [n][512] = [Whi(256) | Wlo(256)]  (W transposed)
__device__ int    g_node[MAXNNZ];
__device__ int    g_edge[MAXNNZ];
__device__ int    g_adj_e[MAXNNZ];
__device__ int    g_adj_n[MAXNNZ];
__device__ int    g_off_e[MAXN + 1];
__device__ int    g_off_n[MAXN + 1];
__device__ int    g_cur_e[MAXN];
__device__ int    g_cur_n[MAXN];
__device__ int    g_bsum[256];
__device__ int    g_is64;

// ===================== graph preprocessing ===================================
__global__ void k_detect(const unsigned int* __restrict__ raw) {
    if (threadIdx.x == 0 && blockIdx.x == 0) {
        int is64 = 1;
        #pragma unroll 1
        for (int k = 1; k < 256; k += 2)
            if (raw[k] != 0u) { is64 = 0; break; }
        g_is64 = is64;
    }
}

__global__ void k_zero_off(int n) {
    int i = blockIdx.x * blockDim.x + threadIdx.x;
    if (i <= n) { g_off_e[i] = 0; g_off_n[i] = 0; }
}

__global__ void k_convert_hist(const void* __restrict__ raw, int nnz) {
    int i = blockIdx.x * blockDim.x + threadIdx.x;
    if (i >= nnz) return;
    int node, edge;
    if (g_is64) {
        const long long* p = (const long long*)raw;
        node = (int)p[i]; edge = (int)p[nnz + i];
    } else {
        const int* p = (const int*)raw;
        node = p[i]; edge = p[nnz + i];
    }
    g_node[i] = node; g_edge[i] = edge;
    atomicAdd(&g_off_n[node], 1);
    atomicAdd(&g_off_e[edge], 1);
}

#define SCAN_B 1024
__global__ void k_scan_blk(int* __restrict__ a, int n) {
    __shared__ int sh[SCAN_B];
    int i = blockIdx.x * SCAN_B + threadIdx.x;
    int v = (i < n) ? a[i] : 0;
    sh[threadIdx.x] = v;
    __syncthreads();
    #pragma unroll 1
    for (int d = 1; d < SCAN_B; d <<= 1) {
        int t = (threadIdx.x >= d) ? sh[threadIdx.x - d] : 0;
        __syncthreads();
        sh[threadIdx.x] += t;
        __syncthreads();
    }
    if (i < n) a[i] = sh[threadIdx.x] - v;
    if (threadIdx.x == SCAN_B - 1) g_bsum[blockIdx.x] = sh[SCAN_B - 1];
}

__global__ void k_scan_top(int nb) {
    __shared__ int sh[256];
    int v = (threadIdx.x < nb) ? g_bsum[threadIdx.x] : 0;
    sh[threadIdx.x] = v;
    __syncthreads();
    #pragma unroll 1
    for (int d = 1; d < 256; d <<= 1) {
        int t = (threadIdx.x >= d) ? sh[threadIdx.x - d] : 0;
        __syncthreads();
        sh[threadIdx.x] += t;
        __syncthreads();
    }
    if (threadIdx.x < nb) g_bsum[threadIdx.x] = sh[threadIdx.x] - v;
}

__global__ void k_scan_add(int* __restrict__ a, int* __restrict__ cur, int n, int nnz) {
    int i = blockIdx.x * blockDim.x + threadIdx.x;
    if (i < n) {
        int o = a[i] + g_bsum[i >> 10];
        a[i] = o; cur[i] = o;
    }
    if (i == 0) a[n] = nnz;
}

__global__ void k_fill(int nnz) {
    int i = blockIdx.x * blockDim.x + threadIdx.x;
    if (i >= nnz) return;
    int node = g_node[i];
    int edge = g_edge[i];
    g_adj_e[atomicAdd(&g_cur_e[edge], 1)] = node;
    g_adj_n[atomicAdd(&g_cur_n[node], 1)] = edge;
}

// ===================== phase 1: esum[e] = Binv * sum x[i] ====================
__global__ void __launch_bounds__(256) k_phase1(const float4* __restrict__ x4, int E) {
    int g    = (blockIdx.x * blockDim.x + threadIdx.x) >> 5;
    int lane = threadIdx.x & 31;
    if (g >= E) return;
    int s = g_off_e[g], t = g_off_e[g + 1];
    float4 a0 = make_float4(0.f, 0.f, 0.f, 0.f);
    float4 a1 = make_float4(0.f, 0.f, 0.f, 0.f);
    #pragma unroll 2
    for (int j = s; j < t; j++) {
        const float4* r = x4 + (size_t)g_adj_e[j] * 64;
        float4 v0 = __ldg(r + lane);
        float4 v1 = __ldg(r + lane + 32);
        a0.x += v0.x; a0.y += v0.y; a0.z += v0.z; a0.w += v0.w;
        a1.x += v1.x; a1.y += v1.y; a1.z += v1.z; a1.w += v1.w;
    }
    float binv = (t > s) ? 1.0f / (float)(t - s) : 0.f;
    a0.x *= binv; a0.y *= binv; a0.z *= binv; a0.w *= binv;
    a1.x *= binv; a1.y *= binv; a1.z *= binv; a1.w *= binv;
    float4* o = (float4*)g_esum + (size_t)g * 64;
    o[lane]      = a0;
    o[lane + 32] = a1;
}

// ===================== phase 2: agg -> fp16 hi/lo ============================
__device__ __forceinline__ void write_hilo(__half* p, int k, float4 v) {
    __half h0 = __float2half_rn(v.x), h1 = __float2half_rn(v.y);
    __half h2 = __float2half_rn(v.z), h3 = __float2half_rn(v.w);
    __half l0 = __float2half_rn(v.x - __half2float(h0));
    __half l1 = __float2half_rn(v.y - __half2float(h1));
    __half l2 = __float2half_rn(v.z - __half2float(h2));
    __half l3 = __float2half_rn(v.w - __half2float(h3));
    __half2 hA = __halves2half2(h0, h1), hB = __halves2half2(h2, h3);
    __half2 lA = __halves2half2(l0, l1), lB = __halves2half2(l2, l3);
    *(__half2*)(p + k)           = hA; *(__half2*)(p + k + 2)       = hB;
    *(__half2*)(p + 256 + k)     = lA; *(__half2*)(p + 256 + k + 2) = lB;
}

__global__ void __launch_bounds__(256) k_phase2(const float* __restrict__ hw, int N) {
    int g    = (blockIdx.x * blockDim.x + threadIdx.x) >> 5;
    int lane = threadIdx.x & 31;
    if (g >= N) return;
    int s = g_off_n[g], t = g_off_n[g + 1];
    float4 a0 = make_float4(0.f, 0.f, 0.f, 0.f);
    float4 a1 = make_float4(0.f, 0.f, 0.f, 0.f);
    float d = 0.f;
    #pragma unroll 2
    for (int j = s; j < t; j++) {
        int e = g_adj_n[j];
        d += __ldg(&hw[e]);
        const float4* r = (const float4*)g_esum + (size_t)e * 64;
        float4 v0 = __ldg(r + lane);
        float4 v1 = __ldg(r + lane + 32);
        a0.x += v0.x; a0.y += v0.y; a0.z += v0.z; a0.w += v0.w;
        a1.x += v1.x; a1.y += v1.y; a1.z += v1.z; a1.w += v1.w;
    }
    float dinv = (d > 0.f) ? 1.0f / d : 0.f;
    a0.x *= dinv; a0.y *= dinv; a0.z *= dinv; a0.w *= dinv;
    a1.x *= dinv; a1.y *= dinv; a1.z *= dinv; a1.w *= dinv;
    __half* p = g_Ah + (size_t)g * 512;
    write_hilo(p, lane * 4, a0);
    write_hilo(p, 128 + lane * 4, a1);
}

// ===================== W -> B (transpose + hi/lo split) ======================
__global__ void k_convW(const float* __restrict__ W) {
    int i = blockIdx.x * blockDim.x + threadIdx.x;   // 65536
    if (i >= 65536) return;
    int n  = i & 255;
    int kk = i >> 8;
    float v = __ldg(&W[kk * 256 + n]);
    __half hi = __float2half_rn(v);
    __half lo = __float2half_rn(v - __half2float(hi));
    __half* p = g_Bh + (size_t)n * 512;
    p[kk]       = hi;
    p[256 + kk] = lo;
}

// ===================== mma.sync GEMM =========================================
// C[M,256] = A''[M,768] · B''[256,768]^T + bias, realized over [hi|lo] storage.
// CTA tile 128x128, 8 warps (2x4), warp tile 64x32, BK=32, double-buffered.
#define ASTR 40   // smem row stride in halves (32 + 8 pad) -> conflict-free ldmatrix

__device__ __forceinline__ void ldsm_x4(uint32_t& r0, uint32_t& r1,
                                        uint32_t& r2, uint32_t& r3, uint32_t a) {
    asm volatile("ldmatrix.sync.aligned.m8n8.x4.shared.b16 {%0,%1,%2,%3}, [%4];"
                 : "=r"(r0), "=r"(r1), "=r"(r2), "=r"(r3) : "r"(a));
}
__device__ __forceinline__ void mma16816(float* c, const uint32_t* a, const uint32_t* b) {
    asm volatile("mma.sync.aligned.m16n8k16.row.col.f32.f16.f16.f32 "
                 "{%0,%1,%2,%3}, {%4,%5,%6,%7}, {%8,%9}, {%0,%1,%2,%3};"
                 : "+f"(c[0]), "+f"(c[1]), "+f"(c[2]), "+f"(c[3])
                 : "r"(a[0]), "r"(a[1]), "r"(a[2]), "r"(a[3]), "r"(b[0]), "r"(b[1]));
}
__device__ __forceinline__ uint32_t smem_u32(const void* p) {
    uint32_t a;
    asm("{ .reg .u64 t; cvta.to.shared.u64 t, %1; cvt.u32.u64 %0, t; }"
        : "=r"(a) : "l"(p));
    return a;
}

__global__ void __launch_bounds__(256) k_gemm_mma(
    const float* __restrict__ bias, float* __restrict__ C, int M)
{
    __shared__ __align__(16) __half sA[2][128 * ASTR];
    __shared__ __align__(16) __half sB[2][128 * ASTR];

    int tid  = threadIdx.x;
    int wid  = tid >> 5;
    int lane = tid & 31;
    int m0   = blockIdx.y * 128;
    int n0   = blockIdx.x * 128;
    int wm   = (wid >> 2) * 64;      // warp M offset within CTA
    int wn   = (wid & 3) * 32;       // warp N offset within CTA

    float acc[4][4][4];
    #pragma unroll
    for (int i = 0; i < 4; i++)
        #pragma unroll
        for (int j = 0; j < 4; j++)
            #pragma unroll
            for (int r = 0; r < 4; r++) acc[i][j][r] = 0.f;

    // loader indexing: 2 uint4 per thread per matrix per chunk
    int lm = tid >> 1;               // row 0..127
    int lq = (tid & 1) * 2;          // uint4 pair index {0,1} base

    // ldmatrix source addresses (per-lane, fixed offsets within tile)
    int a_row = wm + (lane & 15);
    int a_colx = (lane >> 4) << 3;
    int b_row = wn + (lane & 7) + ((lane >> 4) << 3);
    int b_colx = ((lane >> 3) & 1) << 3;

    const uint4* Ag = (const uint4*)g_Ah;
    const uint4* Bg = (const uint4*)g_Bh;

    uint4 ra[2], rb[2];

    // chunk c in [0,24): term t = c>>3, kc = c&7
    //   A col-chunk = (t==1)? kc+8 : kc ;  B col-chunk = (t==2)? kc+8 : kc
    #pragma unroll 1
    for (int c = 0; c < 24; c++) {
        int t  = c >> 3, kc = c & 7;
        int ak = (t == 1) ? kc + 8 : kc;
        int bk = (t == 2) ? kc + 8 : kc;

        if (c == 0) {
            // prologue load chunk 0 into buf 0
            #pragma unroll
            for (int i = 0; i < 2; i++) {
                int gm = m0 + lm;
                ra[i] = (gm < M) ? __ldg(Ag + (size_t)gm * 64 + ak * 4 + lq + i)
                                 : make_uint4(0u, 0u, 0u, 0u);
                rb[i] = __ldg(Bg + (size_t)(n0 + lm) * 64 + bk * 4 + lq + i);
            }
            #pragma unroll
            for (int i = 0; i < 2; i++) {
                *(uint4*)(sA[0] + lm * ASTR + (lq + i) * 8) = ra[i];
                *(uint4*)(sB[0] + lm * ASTR + (lq + i) * 8) = rb[i];
            }
            __syncthreads();
        }

        // prefetch next chunk into registers
        if (c + 1 < 24) {
            int c2 = c + 1;
            int t2 = c2 >> 3, kc2 = c2 & 7;
            int ak2 = (t2 == 1) ? kc2 + 8 : kc2;
            int bk2 = (t2 == 2) ? kc2 + 8 : kc2;
            #pragma unroll
            for (int i = 0; i < 2; i++) {
                int gm = m0 + lm;
                ra[i] = (gm < M) ? __ldg(Ag + (size_t)gm * 64 + ak2 * 4 + lq + i)
                                 : make_uint4(0u, 0u, 0u, 0u);
                rb[i] = __ldg(Bg + (size_t)(n0 + lm) * 64 + bk2 * 4 + lq + i);
            }
        }

        // compute on buf (c&1)
        {
            int buf = c & 1;
            uint32_t sAb = smem_u32(sA[buf]);
            uint32_t sBb = smem_u32(sB[buf]);
            #pragma unroll
            for (int ks = 0; ks < 32; ks += 16) {
                uint32_t afr[4][4];
                #pragma unroll
                for (int f = 0; f < 4; f++) {
                    uint32_t addr = sAb + ((a_row + f * 16) * ASTR + ks + a_colx) * 2;
                    ldsm_x4(afr[f][0], afr[f][1], afr[f][2], afr[f][3], addr);
                }
                uint32_t bfr[4][2];
                #pragma unroll
                for (int h = 0; h < 2; h++) {
                    uint32_t addr = sBb + ((b_row + h * 16) * ASTR + ks + b_colx) * 2;
                    ldsm_x4(bfr[h * 2][0], bfr[h * 2][1],
                            bfr[h * 2 + 1][0], bfr[h * 2 + 1][1], addr);
                }
                #pragma unroll
                for (int mf = 0; mf < 4; mf++)
                    #pragma unroll
                    for (int nf = 0; nf < 4; nf++)
                        mma16816(acc[mf][nf], afr[mf], bfr[nf]);
            }
        }

        // store prefetched chunk into other buffer
        if (c + 1 < 24) {
            int buf = (c + 1) & 1;
            #pragma unroll
            for (int i = 0; i < 2; i++) {
                *(uint4*)(sA[buf] + lm * ASTR + (lq + i) * 8) = ra[i];
                *(uint4*)(sB[buf] + lm * ASTR + (lq + i) * 8) = rb[i];
            }
            __syncthreads();
        }
    }

    // epilogue: C = acc + bias
    float bv[8];
    #pragma unroll
    for (int nf = 0; nf < 4; nf++) {
        int gc = n0 + wn + nf * 8 + (lane & 3) * 2;
        bv[nf * 2]     = __ldg(&bias[gc]);
        bv[nf * 2 + 1] = __ldg(&bias[gc + 1]);
    }
    #pragma unroll
    for (int mf = 0; mf < 4; mf++) {
        int gr0 = m0 + wm + mf * 16 + (lane >> 2);
        #pragma unroll
        for (int nf = 0; nf < 4; nf++) {
            int gc = n0 + wn + nf * 8 + (lane & 3) * 2;
            if (gr0 < M) {
                float2 o0 = make_float2(acc[mf][nf][0] + bv[nf * 2],
                                        acc[mf][nf][1] + bv[nf * 2 + 1]);
                *(float2*)(C + (size_t)gr0 * 256 + gc) = o0;
            }
            if (gr0 + 8 < M) {
                float2 o1 = make_float2(acc[mf][nf][2] + bv[nf * 2],
                                        acc[mf][nf][3] + bv[nf * 2 + 1]);
                *(float2*)(C + (size_t)(gr0 + 8) * 256 + gc) = o1;
            }
        }
    }
}

// ---------------------------------------------------------------------------
static int* sym_ptr(const void* sym) {
    void* p = nullptr;
    cudaGetSymbolAddress(&p, sym);
    return (int*)p;
}

extern "C" void kernel_launch(void* const* d_in, const int* in_sizes, int n_in,
                              void* d_out, int out_size) {
    const float* x    = (const float*)d_in[0];
    const void*  hidx = d_in[1];
    const float* hw   = (const float*)d_in[2];
    const float* W    = (const float*)d_in[3];
    const float* bias = (const float*)d_in[4];
    float*       out  = (float*)d_out;

    int N   = in_sizes[0] / 256;
    int NNZ = in_sizes[1] / 2;
    int E   = in_sizes[2];
    int NE  = (N > E) ? N : E;

    int* p_off_e = sym_ptr(g_off_e);
    int* p_off_n = sym_ptr(g_off_n);
    int* p_cur_e = sym_ptr(g_cur_e);
    int* p_cur_n = sym_ptr(g_cur_n);

    k_detect<<<1, 32>>>((const unsigned int*)hidx);
    k_zero_off<<<(NE + 256) / 256, 256>>>(NE);
    k_convW<<<256, 256>>>(W);
    k_convert_hist<<<(NNZ + 255) / 256, 256>>>(hidx, NNZ);

    int nbE = (E + SCAN_B - 1) / SCAN_B;
    k_scan_blk<<<nbE, SCAN_B>>>(p_off_e, E);
    k_scan_top<<<1, 256>>>(nbE);
    k_scan_add<<<(E + 255) / 256, 256>>>(p_off_e, p_cur_e, E, NNZ);

    int nbN = (N + SCAN_B - 1) / SCAN_B;
    k_scan_blk<<<nbN, SCAN_B>>>(p_off_n, N);
    k_scan_top<<<1, 256>>>(nbN);
    k_scan_add<<<(N + 255) / 256, 256>>>(p_off_n, p_cur_n, N, NNZ);

    k_fill<<<(NNZ + 255) / 256, 256>>>(NNZ);

    k_phase1<<<(E * 32 + 255) / 256, 256>>>((const float4*)x, E);
    k_phase2<<<(N * 32 + 255) / 256, 256>>>(hw, N);

    dim3 g(2, (N + 127) / 128);
    k_gemm_mma<<<g, 256>>>(bias, out, N);
}

// round 6
// speedup vs baseline: 2.1466x; 1.0550x over previous
#include <cuda_runtime.h>
#include <cuda_fp16.h>
#include <cstdint>

// ---------------------------------------------------------------------------
// PyG HypergraphConv:  out = (Dinv ⊙ H · Binv · Hᵀ · x) @ W + b
// CSR two-phase aggregation over fp16 feature rows (halved L2 gather traffic),
// fp32 accumulation, mma.sync fp16 hi/lo split GEMM.
// ---------------------------------------------------------------------------

#define MAXN   50000
#define MAXNNZ 500000

__device__ __half g_x16 [MAXN * 256];
__device__ __half g_es16[MAXN * 256];
__device__ __half g_Ah[MAXN * 512];    // [M][512] = [hi(256) | lo(256)]
__device__ __half g_Bh[256 * 512];     // [n][512] = [Whi(256) | Wlo(256)] (W^T)
__device__ int    g_node[MAXNNZ];
__device__ int    g_edge[MAXNNZ];
__device__ int    g_adj_e[MAXNNZ];
__device__ int    g_adj_n[MAXNNZ];
__device__ int    g_off_e[MAXN + 1];
__device__ int    g_off_n[MAXN + 1];
__device__ int    g_cur_e[MAXN];
__device__ int    g_cur_n[MAXN];
__device__ int    g_bsum[256];
__device__ int    g_is64;

// half2 <-> uint reinterpretation
__device__ __forceinline__ __half2 u2h2(uint32_t u) {
    __half2 h; *(uint32_t*)&h = u; return h;
}
__device__ __forceinline__ uint32_t h22u(__half2 h) {
    return *(uint32_t*)&h;
}

// ===================== graph preprocessing ===================================
__global__ void k_detect(const unsigned int* __restrict__ raw) {
    if (threadIdx.x == 0 && blockIdx.x == 0) {
        int is64 = 1;
        #pragma unroll 1
        for (int k = 1; k < 256; k += 2)
            if (raw[k] != 0u) { is64 = 0; break; }
        g_is64 = is64;
    }
}

__global__ void k_zero_off(int n) {
    int i = blockIdx.x * blockDim.x + threadIdx.x;
    if (i <= n) { g_off_e[i] = 0; g_off_n[i] = 0; }
}

__global__ void k_convert_hist(const void* __restrict__ raw, int nnz) {
    int i = blockIdx.x * blockDim.x + threadIdx.x;
    if (i >= nnz) return;
    int node, edge;
    if (g_is64) {
        const long long* p = (const long long*)raw;
        node = (int)p[i]; edge = (int)p[nnz + i];
    } else {
        const int* p = (const int*)raw;
        node = p[i]; edge = p[nnz + i];
    }
    g_node[i] = node; g_edge[i] = edge;
    atomicAdd(&g_off_n[node], 1);
    atomicAdd(&g_off_e[edge], 1);
}

#define SCAN_B 1024
__global__ void k_scan_blk(int* __restrict__ a, int n) {
    __shared__ int sh[SCAN_B];
    int i = blockIdx.x * SCAN_B + threadIdx.x;
    int v = (i < n) ? a[i] : 0;
    sh[threadIdx.x] = v;
    __syncthreads();
    #pragma unroll 1
    for (int d = 1; d < SCAN_B; d <<= 1) {
        int t = (threadIdx.x >= d) ? sh[threadIdx.x - d] : 0;
        __syncthreads();
        sh[threadIdx.x] += t;
        __syncthreads();
    }
    if (i < n) a[i] = sh[threadIdx.x] - v;
    if (threadIdx.x == SCAN_B - 1) g_bsum[blockIdx.x] = sh[SCAN_B - 1];
}

__global__ void k_scan_top(int nb) {
    __shared__ int sh[256];
    int v = (threadIdx.x < nb) ? g_bsum[threadIdx.x] : 0;
    sh[threadIdx.x] = v;
    __syncthreads();
    #pragma unroll 1
    for (int d = 1; d < 256; d <<= 1) {
        int t = (threadIdx.x >= d) ? sh[threadIdx.x - d] : 0;
        __syncthreads();
        sh[threadIdx.x] += t;
        __syncthreads();
    }
    if (threadIdx.x < nb) g_bsum[threadIdx.x] = sh[threadIdx.x] - v;
}

__global__ void k_scan_add(int* __restrict__ a, int* __restrict__ cur, int n, int nnz) {
    int i = blockIdx.x * blockDim.x + threadIdx.x;
    if (i < n) {
        int o = a[i] + g_bsum[i >> 10];
        a[i] = o; cur[i] = o;
    }
    if (i == 0) a[n] = nnz;
}

__global__ void k_fill(int nnz) {
    int i = blockIdx.x * blockDim.x + threadIdx.x;
    if (i >= nnz) return;
    int node = g_node[i];
    int edge = g_edge[i];
    g_adj_e[atomicAdd(&g_cur_e[edge], 1)] = node;
    g_adj_n[atomicAdd(&g_cur_n[node], 1)] = edge;
}

// ===================== x -> fp16 (sequential, once) ==========================
__global__ void k_convx(const float4* __restrict__ x4, int n4) {
    int i = blockIdx.x * blockDim.x + threadIdx.x;
    if (i >= n4) return;
    float4 v = __ldg(x4 + i);
    uint2 o;
    o.x = h22u(__floats2half2_rn(v.x, v.y));
    o.y = h22u(__floats2half2_rn(v.z, v.w));
    ((uint2*)g_x16)[i] = o;
}

// ===================== phase 1: es16[e] = Binv * sum x16[i] ==================
// Row = 256 halves = 32 uint4s; 32 lanes x 1 uint4 (8 halves) each.
__global__ void __launch_bounds__(256) k_phase1(int E) {
    int g    = (blockIdx.x * blockDim.x + threadIdx.x) >> 5;
    int lane = threadIdx.x & 31;
    if (g >= E) return;
    int s = g_off_e[g], t = g_off_e[g + 1];
    float2 a[4];
    #pragma unroll
    for (int q = 0; q < 4; q++) a[q] = make_float2(0.f, 0.f);
    #pragma unroll 2
    for (int j = s; j < t; j++) {
        uint4 v = __ldg((const uint4*)g_x16 + (size_t)g_adj_e[j] * 32 + lane);
        float2 f0 = __half22float2(u2h2(v.x));
        float2 f1 = __half22float2(u2h2(v.y));
        float2 f2 = __half22float2(u2h2(v.z));
        float2 f3 = __half22float2(u2h2(v.w));
        a[0].x += f0.x; a[0].y += f0.y;
        a[1].x += f1.x; a[1].y += f1.y;
        a[2].x += f2.x; a[2].y += f2.y;
        a[3].x += f3.x; a[3].y += f3.y;
    }
    float binv = (t > s) ? 1.0f / (float)(t - s) : 0.f;
    uint4 o;
    o.x = h22u(__floats2half2_rn(a[0].x * binv, a[0].y * binv));
    o.y = h22u(__floats2half2_rn(a[1].x * binv, a[1].y * binv));
    o.z = h22u(__floats2half2_rn(a[2].x * binv, a[2].y * binv));
    o.w = h22u(__floats2half2_rn(a[3].x * binv, a[3].y * binv));
    ((uint4*)g_es16)[(size_t)g * 32 + lane] = o;
}

// ===================== phase 2: agg -> fp16 hi/lo ============================
__global__ void __launch_bounds__(256) k_phase2(const float* __restrict__ hw, int N) {
    int g    = (blockIdx.x * blockDim.x + threadIdx.x) >> 5;
    int lane = threadIdx.x & 31;
    if (g >= N) return;
    int s = g_off_n[g], t = g_off_n[g + 1];
    float2 a[4];
    #pragma unroll
    for (int q = 0; q < 4; q++) a[q] = make_float2(0.f, 0.f);
    float d = 0.f;
    #pragma unroll 2
    for (int j = s; j < t; j++) {
        int e = g_adj_n[j];
        d += __ldg(&hw[e]);
        uint4 v = __ldg((const uint4*)g_es16 + (size_t)e * 32 + lane);
        float2 f0 = __half22float2(u2h2(v.x));
        float2 f1 = __half22float2(u2h2(v.y));
        float2 f2 = __half22float2(u2h2(v.z));
        float2 f3 = __half22float2(u2h2(v.w));
        a[0].x += f0.x; a[0].y += f0.y;
        a[1].x += f1.x; a[1].y += f1.y;
        a[2].x += f2.x; a[2].y += f2.y;
        a[3].x += f3.x; a[3].y += f3.y;
    }
    float dinv = (d > 0.f) ? 1.0f / d : 0.f;
    float f[8];
    f[0] = a[0].x * dinv; f[1] = a[0].y * dinv;
    f[2] = a[1].x * dinv; f[3] = a[1].y * dinv;
    f[4] = a[2].x * dinv; f[5] = a[2].y * dinv;
    f[6] = a[3].x * dinv; f[7] = a[3].y * dinv;

    __half hi[8]; float lo[8];
    #pragma unroll
    for (int q = 0; q < 8; q++) {
        hi[q] = __float2half_rn(f[q]);
        lo[q] = f[q] - __half2float(hi[q]);
    }
    uint4 oh, ol;
    oh.x = h22u(__halves2half2(hi[0], hi[1]));
    oh.y = h22u(__halves2half2(hi[2], hi[3]));
    oh.z = h22u(__halves2half2(hi[4], hi[5]));
    oh.w = h22u(__halves2half2(hi[6], hi[7]));
    ol.x = h22u(__floats2half2_rn(lo[0], lo[1]));
    ol.y = h22u(__floats2half2_rn(lo[2], lo[3]));
    ol.z = h22u(__floats2half2_rn(lo[4], lo[5]));
    ol.w = h22u(__floats2half2_rn(lo[6], lo[7]));
    // A row = 512 halves = 64 uint4s: hi at [0,32), lo at [32,64)
    uint4* p = (uint4*)(g_Ah + (size_t)g * 512);
    p[lane]      = oh;
    p[lane + 32] = ol;
}

// ===================== W -> B (transpose + hi/lo split) ======================
__global__ void k_convW(const float* __restrict__ W) {
    int i = blockIdx.x * blockDim.x + threadIdx.x;
    if (i >= 65536) return;
    int n  = i & 255;
    int kk = i >> 8;
    float v = __ldg(&W[kk * 256 + n]);
    __half hi = __float2half_rn(v);
    __half lo = __float2half_rn(v - __half2float(hi));
    __half* p = g_Bh + (size_t)n * 512;
    p[kk]       = hi;
    p[256 + kk] = lo;
}

// ===================== mma.sync GEMM =========================================
#define ASTR 40

__device__ __forceinline__ void ldsm_x4(uint32_t& r0, uint32_t& r1,
                                        uint32_t& r2, uint32_t& r3, uint32_t a) {
    asm volatile("ldmatrix.sync.aligned.m8n8.x4.shared.b16 {%0,%1,%2,%3}, [%4];"
                 : "=r"(r0), "=r"(r1), "=r"(r2), "=r"(r3) : "r"(a));
}
__device__ __forceinline__ void mma16816(float* c, const uint32_t* a, const uint32_t* b) {
    asm volatile("mma.sync.aligned.m16n8k16.row.col.f32.f16.f16.f32 "
                 "{%0,%1,%2,%3}, {%4,%5,%6,%7}, {%8,%9}, {%0,%1,%2,%3};"
                 : "+f"(c[0]), "+f"(c[1]), "+f"(c[2]), "+f"(c[3])
                 : "r"(a[0]), "r"(a[1]), "r"(a[2]), "r"(a[3]), "r"(b[0]), "r"(b[1]));
}
__device__ __forceinline__ uint32_t smem_u32(const void* p) {
    uint32_t a;
    asm("{ .reg .u64 t; cvta.to.shared.u64 t, %1; cvt.u32.u64 %0, t; }"
        : "=r"(a) : "l"(p));
    return a;
}

__global__ void __launch_bounds__(256) k_gemm_mma(
    const float* __restrict__ bias, float* __restrict__ C, int M)
{
    __shared__ __align__(16) __half sA[2][128 * ASTR];
    __shared__ __align__(16) __half sB[2][128 * ASTR];

    int tid  = threadIdx.x;
    int wid  = tid >> 5;
    int lane = tid & 31;
    int m0   = blockIdx.y * 128;
    int n0   = blockIdx.x * 128;
    int wm   = (wid >> 2) * 64;
    int wn   = (wid & 3) * 32;

    float acc[4][4][4];
    #pragma unroll
    for (int i = 0; i < 4; i++)
        #pragma unroll
        for (int j = 0; j < 4; j++)
            #pragma unroll
            for (int r = 0; r < 4; r++) acc[i][j][r] = 0.f;

    int lm = tid >> 1;
    int lq = (tid & 1) * 2;

    int a_row = wm + (lane & 15);
    int a_colx = (lane >> 4) << 3;
    int b_row = wn + (lane & 7) + ((lane >> 4) << 3);
    int b_colx = ((lane >> 3) & 1) << 3;

    const uint4* Ag = (const uint4*)g_Ah;
    const uint4* Bg = (const uint4*)g_Bh;

    uint4 ra[2], rb[2];

    #pragma unroll 1
    for (int c = 0; c < 24; c++) {
        int t  = c >> 3, kc = c & 7;
        int ak = (t == 1) ? kc + 8 : kc;
        int bk = (t == 2) ? kc + 8 : kc;

        if (c == 0) {
            #pragma unroll
            for (int i = 0; i < 2; i++) {
                int gm = m0 + lm;
                ra[i] = (gm < M) ? __ldg(Ag + (size_t)gm * 64 + ak * 4 + lq + i)
                                 : make_uint4(0u, 0u, 0u, 0u);
                rb[i] = __ldg(Bg + (size_t)(n0 + lm) * 64 + bk * 4 + lq + i);
            }
            #pragma unroll
            for (int i = 0; i < 2; i++) {
                *(uint4*)(sA[0] + lm * ASTR + (lq + i) * 8) = ra[i];
                *(uint4*)(sB[0] + lm * ASTR + (lq + i) * 8) = rb[i];
            }
            __syncthreads();
        }

        if (c + 1 < 24) {
            int c2 = c + 1;
            int t2 = c2 >> 3, kc2 = c2 & 7;
            int ak2 = (t2 == 1) ? kc2 + 8 : kc2;
            int bk2 = (t2 == 2) ? kc2 + 8 : kc2;
            #pragma unroll
            for (int i = 0; i < 2; i++) {
                int gm = m0 + lm;
                ra[i] = (gm < M) ? __ldg(Ag + (size_t)gm * 64 + ak2 * 4 + lq + i)
                                 : make_uint4(0u, 0u, 0u, 0u);
                rb[i] = __ldg(Bg + (size_t)(n0 + lm) * 64 + bk2 * 4 + lq + i);
            }
        }

        {
            int buf = c & 1;
            uint32_t sAb = smem_u32(sA[buf]);
            uint32_t sBb = smem_u32(sB[buf]);
            #pragma unroll
            for (int ks = 0; ks < 32; ks += 16) {
                uint32_t afr[4][4];
                #pragma unroll
                for (int f = 0; f < 4; f++) {
                    uint32_t addr = sAb + ((a_row + f * 16) * ASTR + ks + a_colx) * 2;
                    ldsm_x4(afr[f][0], afr[f][1], afr[f][2], afr[f][3], addr);
                }
                uint32_t bfr[4][2];
                #pragma unroll
                for (int h = 0; h < 2; h++) {
                    uint32_t addr = sBb + ((b_row + h * 16) * ASTR + ks + b_colx) * 2;
                    ldsm_x4(bfr[h * 2][0], bfr[h * 2][1],
                            bfr[h * 2 + 1][0], bfr[h * 2 + 1][1], addr);
                }
                #pragma unroll
                for (int mf = 0; mf < 4; mf++)
                    #pragma unroll
                    for (int nf = 0; nf < 4; nf++)
                        mma16816(acc[mf][nf], afr[mf], bfr[nf]);
            }
        }

        if (c + 1 < 24) {
            int buf = (c + 1) & 1;
            #pragma unroll
            for (int i = 0; i < 2; i++) {
                *(uint4*)(sA[buf] + lm * ASTR + (lq + i) * 8) = ra[i];
                *(uint4*)(sB[buf] + lm * ASTR + (lq + i) * 8) = rb[i];
            }
            __syncthreads();
        }
    }

    float bv[8];
    #pragma unroll
    for (int nf = 0; nf < 4; nf++) {
        int gc = n0 + wn + nf * 8 + (lane & 3) * 2;
        bv[nf * 2]     = __ldg(&bias[gc]);
        bv[nf * 2 + 1] = __ldg(&bias[gc + 1]);
    }
    #pragma unroll
    for (int mf = 0; mf < 4; mf++) {
        int gr0 = m0 + wm + mf * 16 + (lane >> 2);
        #pragma unroll
        for (int nf = 0; nf < 4; nf++) {
            int gc = n0 + wn + nf * 8 + (lane & 3) * 2;
            if (gr0 < M) {
                float2 o0 = make_float2(acc[mf][nf][0] + bv[nf * 2],
                                        acc[mf][nf][1] + bv[nf * 2 + 1]);
                *(float2*)(C + (size_t)gr0 * 256 + gc) = o0;
            }
            if (gr0 + 8 < M) {
                float2 o1 = make_float2(acc[mf][nf][2] + bv[nf * 2],
                                        acc[mf][nf][3] + bv[nf * 2 + 1]);
                *(float2*)(C + (size_t)(gr0 + 8) * 256 + gc) = o1;
            }
        }
    }
}

// ---------------------------------------------------------------------------
static int* sym_ptr(const void* sym) {
    void* p = nullptr;
    cudaGetSymbolAddress(&p, sym);
    return (int*)p;
}

extern "C" void kernel_launch(void* const* d_in, const int* in_sizes, int n_in,
                              void* d_out, int out_size) {
    const float* x    = (const float*)d_in[0];
    const void*  hidx = d_in[1];
    const float* hw   = (const float*)d_in[2];
    const float* W    = (const float*)d_in[3];
    const float* bias = (const float*)d_in[4];
    float*       out  = (float*)d_out;

    int N   = in_sizes[0] / 256;
    int NNZ = in_sizes[1] / 2;
    int E   = in_sizes[2];
    int NE  = (N > E) ? N : E;

    int* p_off_e = sym_ptr(g_off_e);
    int* p_off_n = sym_ptr(g_off_n);
    int* p_cur_e = sym_ptr(g_cur_e);
    int* p_cur_n = sym_ptr(g_cur_n);

    k_detect<<<1, 32>>>((const unsigned int*)hidx);
    k_zero_off<<<(NE + 256) / 256, 256>>>(NE);
    k_convW<<<256, 256>>>(W);
    int n4 = N * 64;
    k_convx<<<(n4 + 255) / 256, 256>>>((const float4*)x, n4);
    k_convert_hist<<<(NNZ + 255) / 256, 256>>>(hidx, NNZ);

    int nbE = (E + SCAN_B - 1) / SCAN_B;
    k_scan_blk<<<nbE, SCAN_B>>>(p_off_e, E);
    k_scan_top<<<1, 256>>>(nbE);
    k_scan_add<<<(E + 255) / 256, 256>>>(p_off_e, p_cur_e, E, NNZ);

    int nbN = (N + SCAN_B - 1) / SCAN_B;
    k_scan_blk<<<nbN, SCAN_B>>>(p_off_n, N);
    k_scan_top<<<1, 256>>>(nbN);
    k_scan_add<<<(N + 255) / 256, 256>>>(p_off_n, p_cur_n, N, NNZ);

    k_fill<<<(NNZ + 255) / 256, 256>>>(NNZ);

    k_phase1<<<(E * 32 + 255) / 256, 256>>>(E);
    k_phase2<<<(N * 32 + 255) / 256, 256>>>(hw, N);

    dim3 g(2, (N + 127) / 128);
    k_gemm_mma<<<g, 256>>>(bias, out, N);
}

// round 7
// speedup vs baseline: 3.3390x; 1.5555x over previous
#include <cuda_runtime.h>
#include <cuda_fp16.h>
#include <cstdint>

// ---------------------------------------------------------------------------
// PyG HypergraphConv:  out = (Dinv ⊙ H · Binv · Hᵀ · x) @ W + b
// CSR two-phase aggregation over fp16 rows, fp32 accumulation,
// single-term fp16 mma.sync GEMM (K=256). Fused prep kernels.
// ---------------------------------------------------------------------------

#define MAXN   50000
#define MAXNNZ 500000

__device__ __half g_x16 [MAXN * 256];
__device__ __half g_es16[MAXN * 256];
__device__ __half g_A16 [MAXN * 256];   // agg rounded to fp16
__device__ __half g_B16 [256 * 256];    // W^T rounded to fp16
__device__ int    g_node[MAXNNZ];
__device__ int    g_edge[MAXNNZ];
__device__ int    g_adj_e[MAXNNZ];
__device__ int    g_adj_n[MAXNNZ];
__device__ int    g_off_e[MAXN + 1];
__device__ int    g_off_n[MAXN + 1];
__device__ int    g_cur_e[MAXN];
__device__ int    g_cur_n[MAXN];
__device__ int    g_bsum[256];          // [0..127] edge blocks, [128..255] node blocks
__device__ int    g_is64;

__device__ __forceinline__ __half2 u2h2(uint32_t u) {
    __half2 h; *(uint32_t*)&h = u; return h;
}
__device__ __forceinline__ uint32_t h22u(__half2 h) {
    return *(uint32_t*)&h;
}

// ===================== fused init: detect + zero_off + convW + convx =========
// grid.x = b_convx + b_convW + b_zero ; region selected by blockIdx.x
__global__ void k_init(const float4* __restrict__ x4, int n4,
                       const float* __restrict__ W,
                       const unsigned int* __restrict__ raw,
                       int NE, int b_convx, int b_convW) {
    int bx = blockIdx.x;
    if (bx < b_convx) {
        int i = bx * blockDim.x + threadIdx.x;
        if (i < n4) {
            float4 v = __ldg(x4 + i);
            uint2 o;
            o.x = h22u(__floats2half2_rn(v.x, v.y));
            o.y = h22u(__floats2half2_rn(v.z, v.w));
            ((uint2*)g_x16)[i] = o;
        }
        return;
    }
    bx -= b_convx;
    if (bx < b_convW) {
        int i = bx * blockDim.x + threadIdx.x;   // 65536 elements
        if (i < 65536) {
            int n  = i & 255;
            int kk = i >> 8;
            g_B16[(size_t)n * 256 + kk] = __float2half_rn(__ldg(&W[kk * 256 + n]));
        }
        return;
    }
    bx -= b_convW;
    {
        int i = bx * blockDim.x + threadIdx.x;
        if (i <= NE) { g_off_e[i] = 0; g_off_n[i] = 0; }
        if (bx == 0 && threadIdx.x == 0) {
            int is64 = 1;
            #pragma unroll 1
            for (int k = 1; k < 256; k += 2)
                if (raw[k] != 0u) { is64 = 0; break; }
            g_is64 = is64;
        }
    }
}

// ===================== convert indices + histogram ===========================
__global__ void k_convert_hist(const void* __restrict__ raw, int nnz) {
    int i = blockIdx.x * blockDim.x + threadIdx.x;
    if (i >= nnz) return;
    int node, edge;
    if (g_is64) {
        const long long* p = (const long long*)raw;
        node = (int)p[i]; edge = (int)p[nnz + i];
    } else {
        const int* p = (const int*)raw;
        node = p[i]; edge = p[nnz + i];
    }
    g_node[i] = node; g_edge[i] = edge;
    atomicAdd(&g_off_n[node], 1);
    atomicAdd(&g_off_e[edge], 1);
}

// ===================== dual-array scans (edge=y0, node=y1) ===================
#define SCAN_B 1024
__global__ void k_scan_blk2(int nE, int nN) {
    __shared__ int sh[SCAN_B];
    int y = blockIdx.y;
    int* a = y ? g_off_n : g_off_e;
    int n  = y ? nN : nE;
    int i = blockIdx.x * SCAN_B + threadIdx.x;
    int v = (i < n) ? a[i] : 0;
    sh[threadIdx.x] = v;
    __syncthreads();
    #pragma unroll 1
    for (int d = 1; d < SCAN_B; d <<= 1) {
        int t = (threadIdx.x >= d) ? sh[threadIdx.x - d] : 0;
        __syncthreads();
        sh[threadIdx.x] += t;
        __syncthreads();
    }
    if (i < n) a[i] = sh[threadIdx.x] - v;
    if (threadIdx.x == SCAN_B - 1) g_bsum[y * 128 + blockIdx.x] = sh[SCAN_B - 1];
}

__global__ void k_scan_top2(int nbE, int nbN) {
    __shared__ int sh[128];
    int y  = blockIdx.x;
    int nb = y ? nbN : nbE;
    int v = ((int)threadIdx.x < nb) ? g_bsum[y * 128 + threadIdx.x] : 0;
    sh[threadIdx.x] = v;
    __syncthreads();
    #pragma unroll 1
    for (int d = 1; d < 128; d <<= 1) {
        int t = (threadIdx.x >= d) ? sh[threadIdx.x - d] : 0;
        __syncthreads();
        sh[threadIdx.x] += t;
        __syncthreads();
    }
    if ((int)threadIdx.x < nb) g_bsum[y * 128 + threadIdx.x] = sh[threadIdx.x] - v;
}

__global__ void k_scan_add2(int nE, int nN, int nnz) {
    int y = blockIdx.y;
    int* a   = y ? g_off_n : g_off_e;
    int* cur = y ? g_cur_n : g_cur_e;
    int n    = y ? nN : nE;
    int i = blockIdx.x * blockDim.x + threadIdx.x;
    if (i < n) {
        int o = a[i] + g_bsum[y * 128 + (i >> 10)];
        a[i] = o; cur[i] = o;
    }
    if (i == 0) a[n] = nnz;
}

__global__ void k_fill(int nnz) {
    int i = blockIdx.x * blockDim.x + threadIdx.x;
    if (i >= nnz) return;
    int node = g_node[i];
    int edge = g_edge[i];
    g_adj_e[atomicAdd(&g_cur_e[edge], 1)] = node;
    g_adj_n[atomicAdd(&g_cur_n[node], 1)] = edge;
}

// ===================== phase 1: es16[e] = Binv * sum x16[i] ==================
__global__ void __launch_bounds__(256) k_phase1(int E) {
    int g    = (blockIdx.x * blockDim.x + threadIdx.x) >> 5;
    int lane = threadIdx.x & 31;
    if (g >= E) return;
    int s = g_off_e[g], t = g_off_e[g + 1];
    float2 a[4];
    #pragma unroll
    for (int q = 0; q < 4; q++) a[q] = make_float2(0.f, 0.f);
    #pragma unroll 2
    for (int j = s; j < t; j++) {
        uint4 v = __ldg((const uint4*)g_x16 + (size_t)g_adj_e[j] * 32 + lane);
        float2 f0 = __half22float2(u2h2(v.x));
        float2 f1 = __half22float2(u2h2(v.y));
        float2 f2 = __half22float2(u2h2(v.z));
        float2 f3 = __half22float2(u2h2(v.w));
        a[0].x += f0.x; a[0].y += f0.y;
        a[1].x += f1.x; a[1].y += f1.y;
        a[2].x += f2.x; a[2].y += f2.y;
        a[3].x += f3.x; a[3].y += f3.y;
    }
    float binv = (t > s) ? 1.0f / (float)(t - s) : 0.f;
    uint4 o;
    o.x = h22u(__floats2half2_rn(a[0].x * binv, a[0].y * binv));
    o.y = h22u(__floats2half2_rn(a[1].x * binv, a[1].y * binv));
    o.z = h22u(__floats2half2_rn(a[2].x * binv, a[2].y * binv));
    o.w = h22u(__floats2half2_rn(a[3].x * binv, a[3].y * binv));
    ((uint4*)g_es16)[(size_t)g * 32 + lane] = o;
}

// ===================== phase 2: A16[i] = fp16(Dinv * sum es16[e]) ============
__global__ void __launch_bounds__(256) k_phase2(const float* __restrict__ hw, int N) {
    int g    = (blockIdx.x * blockDim.x + threadIdx.x) >> 5;
    int lane = threadIdx.x & 31;
    if (g >= N) return;
    int s = g_off_n[g], t = g_off_n[g + 1];
    float2 a[4];
    #pragma unroll
    for (int q = 0; q < 4; q++) a[q] = make_float2(0.f, 0.f);
    float d = 0.f;
    #pragma unroll 2
    for (int j = s; j < t; j++) {
        int e = g_adj_n[j];
        d += __ldg(&hw[e]);
        uint4 v = __ldg((const uint4*)g_es16 + (size_t)e * 32 + lane);
        float2 f0 = __half22float2(u2h2(v.x));
        float2 f1 = __half22float2(u2h2(v.y));
        float2 f2 = __half22float2(u2h2(v.z));
        float2 f3 = __half22float2(u2h2(v.w));
        a[0].x += f0.x; a[0].y += f0.y;
        a[1].x += f1.x; a[1].y += f1.y;
        a[2].x += f2.x; a[2].y += f2.y;
        a[3].x += f3.x; a[3].y += f3.y;
    }
    float dinv = (d > 0.f) ? 1.0f / d : 0.f;
    uint4 o;
    o.x = h22u(__floats2half2_rn(a[0].x * dinv, a[0].y * dinv));
    o.y = h22u(__floats2half2_rn(a[1].x * dinv, a[1].y * dinv));
    o.z = h22u(__floats2half2_rn(a[2].x * dinv, a[2].y * dinv));
    o.w = h22u(__floats2half2_rn(a[3].x * dinv, a[3].y * dinv));
    ((uint4*)g_A16)[(size_t)g * 32 + lane] = o;
}

// ===================== mma.sync GEMM: C = A16 · B16^T + bias (K=256) =========
#define ASTR 40

__device__ __forceinline__ void ldsm_x4(uint32_t& r0, uint32_t& r1,
                                        uint32_t& r2, uint32_t& r3, uint32_t a) {
    asm volatile("ldmatrix.sync.aligned.m8n8.x4.shared.b16 {%0,%1,%2,%3}, [%4];"
                 : "=r"(r0), "=r"(r1), "=r"(r2), "=r"(r3) : "r"(a));
}
__device__ __forceinline__ void mma16816(float* c, const uint32_t* a, const uint32_t* b) {
    asm volatile("mma.sync.aligned.m16n8k16.row.col.f32.f16.f16.f32 "
                 "{%0,%1,%2,%3}, {%4,%5,%6,%7}, {%8,%9}, {%0,%1,%2,%3};"
                 : "+f"(c[0]), "+f"(c[1]), "+f"(c[2]), "+f"(c[3])
                 : "r"(a[0]), "r"(a[1]), "r"(a[2]), "r"(a[3]), "r"(b[0]), "r"(b[1]));
}
__device__ __forceinline__ uint32_t smem_u32(const void* p) {
    uint32_t a;
    asm("{ .reg .u64 t; cvta.to.shared.u64 t, %1; cvt.u32.u64 %0, t; }"
        : "=r"(a) : "l"(p));
    return a;
}

__global__ void __launch_bounds__(256) k_gemm_mma(
    const float* __restrict__ bias, float* __restrict__ C, int M)
{
    __shared__ __align__(16) __half sA[2][128 * ASTR];
    __shared__ __align__(16) __half sB[2][128 * ASTR];

    int tid  = threadIdx.x;
    int wid  = tid >> 5;
    int lane = tid & 31;
    int m0   = blockIdx.y * 128;
    int n0   = blockIdx.x * 128;
    int wm   = (wid >> 2) * 64;
    int wn   = (wid & 3) * 32;

    float acc[4][4][4];
    #pragma unroll
    for (int i = 0; i < 4; i++)
        #pragma unroll
        for (int j = 0; j < 4; j++)
            #pragma unroll
            for (int r = 0; r < 4; r++) acc[i][j][r] = 0.f;

    int lm = tid >> 1;
    int lq = (tid & 1) * 2;

    int a_row = wm + (lane & 15);
    int a_colx = (lane >> 4) << 3;
    int b_row = wn + (lane & 7) + ((lane >> 4) << 3);
    int b_colx = ((lane >> 3) & 1) << 3;

    const uint4* Ag = (const uint4*)g_A16;   // row stride 32 uint4
    const uint4* Bg = (const uint4*)g_B16;

    uint4 ra[2], rb[2];

    #pragma unroll 1
    for (int c = 0; c < 8; c++) {
        if (c == 0) {
            #pragma unroll
            for (int i = 0; i < 2; i++) {
                int gm = m0 + lm;
                ra[i] = (gm < M) ? __ldg(Ag + (size_t)gm * 32 + lq + i)
                                 : make_uint4(0u, 0u, 0u, 0u);
                rb[i] = __ldg(Bg + (size_t)(n0 + lm) * 32 + lq + i);
            }
            #pragma unroll
            for (int i = 0; i < 2; i++) {
                *(uint4*)(sA[0] + lm * ASTR + (lq + i) * 8) = ra[i];
                *(uint4*)(sB[0] + lm * ASTR + (lq + i) * 8) = rb[i];
            }
            __syncthreads();
        }

        if (c + 1 < 8) {
            int k4 = (c + 1) * 4;
            #pragma unroll
            for (int i = 0; i < 2; i++) {
                int gm = m0 + lm;
                ra[i] = (gm < M) ? __ldg(Ag + (size_t)gm * 32 + k4 + lq + i)
                                 : make_uint4(0u, 0u, 0u, 0u);
                rb[i] = __ldg(Bg + (size_t)(n0 + lm) * 32 + k4 + lq + i);
            }
        }

        {
            int buf = c & 1;
            uint32_t sAb = smem_u32(sA[buf]);
            uint32_t sBb = smem_u32(sB[buf]);
            #pragma unroll
            for (int ks = 0; ks < 32; ks += 16) {
                uint32_t afr[4][4];
                #pragma unroll
                for (int f = 0; f < 4; f++) {
                    uint32_t addr = sAb + ((a_row + f * 16) * ASTR + ks + a_colx) * 2;
                    ldsm_x4(afr[f][0], afr[f][1], afr[f][2], afr[f][3], addr);
                }
                uint32_t bfr[4][2];
                #pragma unroll
                for (int h = 0; h < 2; h++) {
                    uint32_t addr = sBb + ((b_row + h * 16) * ASTR + ks + b_colx) * 2;
                    ldsm_x4(bfr[h * 2][0], bfr[h * 2][1],
                            bfr[h * 2 + 1][0], bfr[h * 2 + 1][1], addr);
                }
                #pragma unroll
                for (int mf = 0; mf < 4; mf++)
                    #pragma unroll
                    for (int nf = 0; nf < 4; nf++)
                        mma16816(acc[mf][nf], afr[mf], bfr[nf]);
            }
        }

        if (c + 1 < 8) {
            int buf = (c + 1) & 1;
            #pragma unroll
            for (int i = 0; i < 2; i++) {
                *(uint4*)(sA[buf] + lm * ASTR + (lq + i) * 8) = ra[i];
                *(uint4*)(sB[buf] + lm * ASTR + (lq + i) * 8) = rb[i];
            }
            __syncthreads();
        }
    }

    float bv[8];
    #pragma unroll
    for (int nf = 0; nf < 4; nf++) {
        int gc = n0 + wn + nf * 8 + (lane & 3) * 2;
        bv[nf * 2]     = __ldg(&bias[gc]);
        bv[nf * 2 + 1] = __ldg(&bias[gc + 1]);
    }
    #pragma unroll
    for (int mf = 0; mf < 4; mf++) {
        int gr0 = m0 + wm + mf * 16 + (lane >> 2);
        #pragma unroll
        for (int nf = 0; nf < 4; nf++) {
            int gc = n0 + wn + nf * 8 + (lane & 3) * 2;
            if (gr0 < M) {
                float2 o0 = make_float2(acc[mf][nf][0] + bv[nf * 2],
                                        acc[mf][nf][1] + bv[nf * 2 + 1]);
                *(float2*)(C + (size_t)gr0 * 256 + gc) = o0;
            }
            if (gr0 + 8 < M) {
                float2 o1 = make_float2(acc[mf][nf][2] + bv[nf * 2],
                                        acc[mf][nf][3] + bv[nf * 2 + 1]);
                *(float2*)(C + (size_t)(gr0 + 8) * 256 + gc) = o1;
            }
        }
    }
}

// ---------------------------------------------------------------------------
extern "C" void kernel_launch(void* const* d_in, const int* in_sizes, int n_in,
                              void* d_out, int out_size) {
    const float* x    = (const float*)d_in[0];
    const void*  hidx = d_in[1];
    const float* hw   = (const float*)d_in[2];
    const float* W    = (const float*)d_in[3];
    const float* bias = (const float*)d_in[4];
    float*       out  = (float*)d_out;

    int N   = in_sizes[0] / 256;
    int NNZ = in_sizes[1] / 2;
    int E   = in_sizes[2];
    int NE  = (N > E) ? N : E;

    // fused init
    int n4 = N * 64;
    int b_convx = (n4 + 255) / 256;
    int b_convW = 256;
    int b_zero  = (NE + 256) / 256;
    k_init<<<b_convx + b_convW + b_zero, 256>>>(
        (const float4*)x, n4, W, (const unsigned int*)hidx, NE, b_convx, b_convW);

    k_convert_hist<<<(NNZ + 255) / 256, 256>>>(hidx, NNZ);

    int nbE = (E + SCAN_B - 1) / SCAN_B;
    int nbN = (N + SCAN_B - 1) / SCAN_B;
    int nbMax = (nbE > nbN) ? nbE : nbN;
    int nMax  = NE;
    dim3 gs(nbMax, 2);
    k_scan_blk2<<<gs, SCAN_B>>>(E, N);
    k_scan_top2<<<2, 128>>>(nbE, nbN);
    dim3 ga((nMax + 255) / 256, 2);
    k_scan_add2<<<ga, 256>>>(E, N, NNZ);

    k_fill<<<(NNZ + 255) / 256, 256>>>(NNZ);

    k_phase1<<<(E * 32 + 255) / 256, 256>>>(E);
    k_phase2<<<(N * 32 + 255) / 256, 256>>>(hw, N);

    dim3 g(2, (N + 127) / 128);
    k_gemm_mma<<<g, 256>>>(bias, out, N);
}